// round 4
// baseline (speedup 1.0000x reference)
#include <cuda_runtime.h>
#include <math.h>

#define NB 8192
#define TT 21
#define HID 32

// ---------------- scratch (static device allocations; no cudaMalloc) -------
__device__ float d_TW[5000 * 192];      // token-part of layer0 x@Wx (+bias), per dir
__device__ float d_HW[2 * 96];          // hole row x@Wx (+bias), per dir
__device__ float d_TY[TT * NB * 32];    // masked type-max embeddings (t=10 unused)
__device__ float d_XW0[2 * TT * NB * 96];
__device__ float d_Y0[TT * NB * 64];    // layer0 bidir output, time-major
__device__ float d_XW1[2 * TT * NB * 96];
__device__ float d_H[2 * NB * HID];     // recurrent state (reused across layers)
__device__ unsigned d_maskFlags;        // dtype-detection flags for mask buffers

// ---------------- K0: mask dtype detection ---------------------------------
// Scans the first 204800 aligned words (safe for all candidate dtypes:
// uint8 -> 819200 bytes total, int32/float32 -> 819200 words total).
// bit0 set: some word not in {0,1}           -> not int32
// bit1 set: some word not in {0,0x3F800000}  -> not float32
__global__ void k_reset() { d_maskFlags = 0u; }

__global__ void k_detect(const unsigned* __restrict__ m) {
    unsigned f = 0;
    for (int i = blockIdx.x * blockDim.x + threadIdx.x; i < 204800;
         i += gridDim.x * blockDim.x) {
        unsigned w = m[i];
        if (w != 0u && w != 1u) f |= 1u;
        if (w != 0u && w != 0x3F800000u) f |= 2u;
    }
    if (f) atomicOr(&d_maskFlags, f);
}

// ---------------- K1: per-vocab token table + hole row ---------------------
// TW[v][dir*96+j] = bias[j] + sum_{k<128} tok_emb[v][k] * Wx[k][j]
// blockIdx.x == 5000 -> hole row over full 160 dims.
__global__ void k_tables(const float* __restrict__ tok_emb,
                         const float* __restrict__ hole,
                         const float* __restrict__ gk_fw, const float* __restrict__ gb_fw,
                         const float* __restrict__ ck_fw, const float* __restrict__ cb_fw,
                         const float* __restrict__ gk_bw, const float* __restrict__ gb_bw,
                         const float* __restrict__ ck_bw, const float* __restrict__ cb_bw)
{
    __shared__ float s[160];
    int v = blockIdx.x;
    int tid = threadIdx.x;              // 0..191
    bool is_hole = (v == 5000);
    int nk = is_hole ? 160 : 128;
    if (tid < nk) s[tid] = is_hole ? hole[tid] : tok_emb[v * 128 + tid];
    __syncthreads();

    int dir = tid / 96, col = tid % 96;
    const float* gk = dir ? gk_bw : gk_fw;
    const float* ck = dir ? ck_bw : ck_fw;
    const float* gb = dir ? gb_bw : gb_fw;
    const float* cb = dir ? cb_bw : cb_fw;
    const float* w;
    int stride;
    float acc;
    if (col < 64) { w = gk + col;        stride = 64; acc = gb[col]; }
    else          { w = ck + (col - 64); stride = 32; acc = cb[col - 64]; }
    #pragma unroll 8
    for (int k = 0; k < nk; k++) acc = fmaf(s[k], w[k * stride], acc);

    if (is_hole) d_HW[tid] = acc;
    else         d_TW[(size_t)v * 192 + tid] = acc;
}

// ---------------- K2: masked type-max embedding -----------------------------
// One warp per (side, pos, b). Lane = type-embedding dim.
// Mask read mode chosen from d_maskFlags.
__global__ void k_typemax(const int* __restrict__ types_b, const void* __restrict__ mask_b,
                          const int* __restrict__ types_a, const void* __restrict__ mask_a,
                          const float* __restrict__ typ_emb)
{
    unsigned flags = d_maskFlags;
    // mode 1: int32; mode 2: float32; mode 0: uint8
    int mode = ((flags & 1u) == 0u) ? 1 : (((flags & 2u) == 0u) ? 2 : 0);

    int w    = (blockIdx.x * blockDim.x + threadIdx.x) >> 5;
    int lane = threadIdx.x & 31;
    int b    = w & (NB - 1);
    int sp   = w >> 13;                  // 0..19
    int side = sp / 10, pos = sp % 10;
    const int*  ty = side ? types_a : types_b;
    const void* mk = side ? mask_a  : mask_b;
    int base = (b * 10 + pos) * 10;
    float m = -3.402823e38f;
    #pragma unroll
    for (int nt = 0; nt < 10; nt++) {
        int id = ty[base + nt];
        bool valid;
        if (mode == 1)      valid = ((const int*)mk)[base + nt] != 0;
        else if (mode == 2) valid = ((const float*)mk)[base + nt] != 0.0f;
        else                valid = ((const unsigned char*)mk)[base + nt] != 0;
        float pen = valid ? 0.0f : -1000.0f;
        m = fmaxf(m, typ_emb[id * 32 + lane] + pen);
    }
    int t = side ? (11 + pos) : pos;
    d_TY[((size_t)t * NB + b) * 32 + lane] = m;
}

// ---------------- K3: layer0 x-precompute GEMM (K=32 type part) ------------
// XW0[dir][t][b][j] = TY[t][b] @ Wx_type[dir]  + TW[token][dir*96+j]
// 64x96 tile per block; t==10 tiles broadcast the hole row.
__global__ void k_xw0(const int* __restrict__ tok_b, const int* __restrict__ tok_a,
                      const float* __restrict__ gkx_fw, const float* __restrict__ ckx_fw,
                      const float* __restrict__ gkx_bw, const float* __restrict__ ckx_bw)
{
    __shared__ float sA[64][33];
    __shared__ float sW[32][96];
    __shared__ int   sTok[64];
    int dir = blockIdx.y;
    int rt  = blockIdx.x;                // 0..2687
    int t   = rt >> 7;                   // 128 tiles of 64 rows per t
    int b0  = (rt & 127) << 6;
    int tid = threadIdx.x;
    int tx = tid & 15, ty = tid >> 4;
    float* outp = d_XW0 + ((size_t)(dir * TT + t) * NB + b0) * 96;

    if (t == 10) {                       // hole: identical row for all b
        #pragma unroll
        for (int c = 0; c < 6; c++) {
            int col = tx + 16 * c;
            float v = d_HW[dir * 96 + col];
            #pragma unroll
            for (int r = 0; r < 4; r++) outp[(ty * 4 + r) * 96 + col] = v;
        }
        return;
    }

    const float* Abase = d_TY + ((size_t)t * NB + b0) * 32;
    for (int i = tid; i < 64 * 32; i += 256) {
        sA[i >> 5][i & 31] = Abase[i];
    }
    const float* gkx = dir ? gkx_bw : gkx_fw;
    const float* ckx = dir ? ckx_bw : ckx_fw;
    for (int i = tid; i < 32 * 64; i += 256) sW[i >> 6][i & 63]        = gkx[i];
    for (int i = tid; i < 32 * 32; i += 256) sW[i >> 5][64 + (i & 31)] = ckx[i];
    if (tid < 64) {
        int b = b0 + tid;
        sTok[tid] = (t < 10) ? tok_b[b * 10 + t] : tok_a[b * 10 + (t - 11)];
    }
    __syncthreads();

    float acc[4][6];
    #pragma unroll
    for (int r = 0; r < 4; r++)
        #pragma unroll
        for (int c = 0; c < 6; c++) acc[r][c] = 0.0f;

    #pragma unroll
    for (int k = 0; k < 32; k++) {
        float a[4], bv[6];
        #pragma unroll
        for (int r = 0; r < 4; r++) a[r] = sA[ty * 4 + r][k];
        #pragma unroll
        for (int c = 0; c < 6; c++) bv[c] = sW[k][tx + 16 * c];
        #pragma unroll
        for (int r = 0; r < 4; r++)
            #pragma unroll
            for (int c = 0; c < 6; c++) acc[r][c] = fmaf(a[r], bv[c], acc[r][c]);
    }

    #pragma unroll
    for (int r = 0; r < 4; r++) {
        const float* tw = d_TW + (size_t)sTok[ty * 4 + r] * 192 + dir * 96;
        #pragma unroll
        for (int c = 0; c < 6; c++) {
            int col = tx + 16 * c;
            outp[(ty * 4 + r) * 96 + col] = acc[r][c] + tw[col];
        }
    }
}

// ---------------- K4: layer1 x-precompute GEMM (K=64) ----------------------
__global__ void k_xw1(const float* __restrict__ gk_fw, const float* __restrict__ gb_fw,
                      const float* __restrict__ ck_fw, const float* __restrict__ cb_fw,
                      const float* __restrict__ gk_bw, const float* __restrict__ gb_bw,
                      const float* __restrict__ ck_bw, const float* __restrict__ cb_bw)
{
    __shared__ float sA[64][65];
    __shared__ float sW[64][96];
    __shared__ float sBias[96];
    int dir  = blockIdx.y;
    int row0 = blockIdx.x << 6;          // global row in [0, 21*8192)
    int tid = threadIdx.x, tx = tid & 15, ty = tid >> 4;

    const float* gk = dir ? gk_bw : gk_fw;
    const float* ck = dir ? ck_bw : ck_fw;
    const float* gb = dir ? gb_bw : gb_fw;
    const float* cb = dir ? cb_bw : cb_fw;

    const float* Abase = d_Y0 + (size_t)row0 * 64;
    for (int i = tid; i < 64 * 64; i += 256) sA[i >> 6][i & 63]        = Abase[i];
    for (int i = tid; i < 64 * 64; i += 256) sW[i >> 6][i & 63]        = gk[i];
    for (int i = tid; i < 64 * 32; i += 256) sW[i >> 5][64 + (i & 31)] = ck[i];
    if (tid < 96) sBias[tid] = (tid < 64) ? gb[tid] : cb[tid - 64];
    __syncthreads();

    float acc[4][6];
    #pragma unroll
    for (int r = 0; r < 4; r++)
        #pragma unroll
        for (int c = 0; c < 6; c++) acc[r][c] = 0.0f;

    #pragma unroll
    for (int k = 0; k < 64; k++) {
        float a[4], bv[6];
        #pragma unroll
        for (int r = 0; r < 4; r++) a[r] = sA[ty * 4 + r][k];
        #pragma unroll
        for (int c = 0; c < 6; c++) bv[c] = sW[k][tx + 16 * c];
        #pragma unroll
        for (int r = 0; r < 4; r++)
            #pragma unroll
            for (int c = 0; c < 6; c++) acc[r][c] = fmaf(a[r], bv[c], acc[r][c]);
    }

    float* outp = d_XW1 + ((size_t)dir * TT * NB + row0) * 96;
    #pragma unroll
    for (int r = 0; r < 4; r++)
        #pragma unroll
        for (int c = 0; c < 6; c++) {
            int col = tx + 16 * c;
            outp[(ty * 4 + r) * 96 + col] = acc[r][c] + sBias[col];
        }
}

// ---------------- K5: one recurrent GRU step (both directions) -------------
// One warp per batch row. Lane l owns h[l]; shuffle-broadcast for dots.
__global__ void k_step(const float* __restrict__ gkh_fw, const float* __restrict__ ckh_fw,
                       const float* __restrict__ gkh_bw, const float* __restrict__ ckh_bw,
                       int s, int layer, float* __restrict__ final_out)
{
    __shared__ float sWg[32][64];
    __shared__ float sWc[32][32];
    int dir = blockIdx.y;
    int tid = threadIdx.x;
    const float* gkh = dir ? gkh_bw : gkh_fw;
    const float* ckh = dir ? ckh_bw : ckh_fw;
    for (int i = tid; i < 32 * 64; i += 256) sWg[i >> 6][i & 63] = gkh[i];
    for (int i = tid; i < 32 * 32; i += 256) sWc[i >> 5][i & 31] = ckh[i];
    __syncthreads();

    int lane = tid & 31, wid = tid >> 5;
    int b = blockIdx.x * 8 + wid;
    int t = dir ? (20 - s) : s;

    float* hptr = d_H + ((size_t)dir * NB + b) * 32;
    float h = (s == 0) ? 0.0f : hptr[lane];

    const float* xw_all = layer ? d_XW1 : d_XW0;
    const float* xw = xw_all + ((size_t)(dir * TT + t) * NB + b) * 96;
    float ar = xw[lane];
    float au = xw[32 + lane];
    float ac = xw[64 + lane];

    #pragma unroll
    for (int k = 0; k < 32; k++) {
        float hk = __shfl_sync(0xffffffffu, h, k);
        ar = fmaf(hk, sWg[k][lane],      ar);
        au = fmaf(hk, sWg[k][lane + 32], au);
    }
    float r = 1.0f / (1.0f + __expf(-ar));
    float u = 1.0f / (1.0f + __expf(-au));
    float rh = r * h;
    #pragma unroll
    for (int k = 0; k < 32; k++) {
        float rk = __shfl_sync(0xffffffffu, rh, k);
        ac = fmaf(rk, sWc[k][lane], ac);
    }
    float c  = 1.0f - 2.0f / (__expf(2.0f * ac) + 1.0f);   // tanh, saturating-safe
    float hn = u * h + (1.0f - u) * c;

    hptr[lane] = hn;
    if (layer) {
        final_out[((size_t)b * TT + t) * 64 + dir * 32 + lane] = hn;   // [B,21,64]
    } else {
        d_Y0[((size_t)t * NB + b) * 64 + dir * 32 + lane] = hn;        // time-major
    }
}

// ---------------- launch ----------------------------------------------------
extern "C" void kernel_launch(void* const* d_in, const int* in_sizes, int n_in,
                              void* d_out, int out_size)
{
    const int*   tok_b = (const int*)d_in[0];
    const int*   typ_b = (const int*)d_in[1];
    const void*  msk_b = (const void*)d_in[2];
    const int*   tok_a = (const int*)d_in[3];
    const int*   typ_a = (const int*)d_in[4];
    const void*  msk_a = (const void*)d_in[5];
    const float* temb = (const float*)d_in[6];
    const float* yemb = (const float*)d_in[7];
    const float* hole = (const float*)d_in[8];
    const float* gk_fw0 = (const float*)d_in[9];
    const float* gb_fw0 = (const float*)d_in[10];
    const float* ck_fw0 = (const float*)d_in[11];
    const float* cb_fw0 = (const float*)d_in[12];
    const float* gk_bw0 = (const float*)d_in[13];
    const float* gb_bw0 = (const float*)d_in[14];
    const float* ck_bw0 = (const float*)d_in[15];
    const float* cb_bw0 = (const float*)d_in[16];
    const float* gk_fw1 = (const float*)d_in[17];
    const float* gb_fw1 = (const float*)d_in[18];
    const float* ck_fw1 = (const float*)d_in[19];
    const float* cb_fw1 = (const float*)d_in[20];
    const float* gk_bw1 = (const float*)d_in[21];
    const float* gb_bw1 = (const float*)d_in[22];
    const float* ck_bw1 = (const float*)d_in[23];
    const float* cb_bw1 = (const float*)d_in[24];
    float* out = (float*)d_out;

    // 0) detect mask dtype (uint8 vs int32 vs float32)
    k_reset<<<1, 1>>>();
    k_detect<<<148, 256>>>((const unsigned*)msk_b);

    // 1) token table (token part of layer0 x@Wx + bias) + hole row
    k_tables<<<5001, 192>>>(temb, hole,
                            gk_fw0, gb_fw0, ck_fw0, cb_fw0,
                            gk_bw0, gb_bw0, ck_bw0, cb_bw0);

    // 2) masked type-max embeddings
    k_typemax<<<20480, 256>>>(typ_b, msk_b, typ_a, msk_a, yemb);

    // 3) layer0 x-precompute (type part K=32 + token-table gather)
    k_xw0<<<dim3(2688, 2), 256>>>(tok_b, tok_a,
                                  gk_fw0 + 128 * 64, ck_fw0 + 128 * 32,
                                  gk_bw0 + 128 * 64, ck_bw0 + 128 * 32);

    // 4) layer0 recurrence (21 steps, fw+bw in parallel)
    for (int s = 0; s < 21; s++) {
        k_step<<<dim3(1024, 2), 256>>>(gk_fw0 + 160 * 64, ck_fw0 + 160 * 32,
                                       gk_bw0 + 160 * 64, ck_bw0 + 160 * 32,
                                       s, 0, out);
    }

    // 5) layer1 x-precompute (K=64)
    k_xw1<<<dim3(2688, 2), 256>>>(gk_fw1, gb_fw1, ck_fw1, cb_fw1,
                                  gk_bw1, gb_bw1, ck_bw1, cb_bw1);

    // 6) layer1 recurrence, writes final output batch-major
    for (int s = 0; s < 21; s++) {
        k_step<<<dim3(1024, 2), 256>>>(gk_fw1 + 64 * 64, ck_fw1 + 64 * 32,
                                       gk_bw1 + 64 * 64, ck_bw1 + 64 * 32,
                                       s, 1, out);
    }
}

// round 5
// speedup vs baseline: 1.3796x; 1.3796x over previous
#include <cuda_runtime.h>
#include <math.h>

#define NB 8192
#define TT 21
#define HID 32

// ---------------- scratch (static device allocations; no cudaMalloc) -------
__device__ float d_TW[5000 * 192];      // token-part of layer0 x@Wx (+bias), per dir
__device__ float d_HW[2 * 96];          // hole row x@Wx (+bias), per dir
__device__ float d_TY[TT * NB * 32];    // masked type-max embeddings (t=10 unused)
__device__ float d_XW0[2 * TT * NB * 96];
__device__ unsigned d_maskFlags;        // dtype-detection flags for mask buffers

// ---------------- K0: mask dtype detection ---------------------------------
__global__ void k_reset() { d_maskFlags = 0u; }

__global__ void k_detect(const unsigned* __restrict__ m) {
    unsigned f = 0;
    for (int i = blockIdx.x * blockDim.x + threadIdx.x; i < 204800;
         i += gridDim.x * blockDim.x) {
        unsigned w = m[i];
        if (w != 0u && w != 1u) f |= 1u;
        if (w != 0u && w != 0x3F800000u) f |= 2u;
    }
    if (f) atomicOr(&d_maskFlags, f);
}

// ---------------- K1: per-vocab token table + hole row ---------------------
__global__ void k_tables(const float* __restrict__ tok_emb,
                         const float* __restrict__ hole,
                         const float* __restrict__ gk_fw, const float* __restrict__ gb_fw,
                         const float* __restrict__ ck_fw, const float* __restrict__ cb_fw,
                         const float* __restrict__ gk_bw, const float* __restrict__ gb_bw,
                         const float* __restrict__ ck_bw, const float* __restrict__ cb_bw)
{
    __shared__ float s[160];
    int v = blockIdx.x;
    int tid = threadIdx.x;              // 0..191
    bool is_hole = (v == 5000);
    int nk = is_hole ? 160 : 128;
    if (tid < nk) s[tid] = is_hole ? hole[tid] : tok_emb[v * 128 + tid];
    __syncthreads();

    int dir = tid / 96, col = tid % 96;
    const float* gk = dir ? gk_bw : gk_fw;
    const float* ck = dir ? ck_bw : ck_fw;
    const float* gb = dir ? gb_bw : gb_fw;
    const float* cb = dir ? cb_bw : cb_fw;
    const float* w;
    int stride;
    float acc;
    if (col < 64) { w = gk + col;        stride = 64; acc = gb[col]; }
    else          { w = ck + (col - 64); stride = 32; acc = cb[col - 64]; }
    #pragma unroll 8
    for (int k = 0; k < nk; k++) acc = fmaf(s[k], w[k * stride], acc);

    if (is_hole) d_HW[tid] = acc;
    else         d_TW[(size_t)v * 192 + tid] = acc;
}

// ---------------- K2: masked type-max embedding -----------------------------
__global__ void k_typemax(const int* __restrict__ types_b, const void* __restrict__ mask_b,
                          const int* __restrict__ types_a, const void* __restrict__ mask_a,
                          const float* __restrict__ typ_emb)
{
    unsigned flags = d_maskFlags;
    int mode = ((flags & 1u) == 0u) ? 1 : (((flags & 2u) == 0u) ? 2 : 0);

    int w    = (blockIdx.x * blockDim.x + threadIdx.x) >> 5;
    int lane = threadIdx.x & 31;
    int b    = w & (NB - 1);
    int sp   = w >> 13;                  // 0..19
    int side = sp / 10, pos = sp % 10;
    const int*  ty = side ? types_a : types_b;
    const void* mk = side ? mask_a  : mask_b;
    int base = (b * 10 + pos) * 10;
    float m = -3.402823e38f;
    #pragma unroll
    for (int nt = 0; nt < 10; nt++) {
        int id = ty[base + nt];
        bool valid;
        if (mode == 1)      valid = ((const int*)mk)[base + nt] != 0;
        else if (mode == 2) valid = ((const float*)mk)[base + nt] != 0.0f;
        else                valid = ((const unsigned char*)mk)[base + nt] != 0;
        float pen = valid ? 0.0f : -1000.0f;
        m = fmaxf(m, typ_emb[id * 32 + lane] + pen);
    }
    int t = side ? (11 + pos) : pos;
    d_TY[((size_t)t * NB + b) * 32 + lane] = m;
}

// ---------------- K3: layer0 x-precompute GEMM (K=32 type part) ------------
__global__ void k_xw0(const int* __restrict__ tok_b, const int* __restrict__ tok_a,
                      const float* __restrict__ gkx_fw, const float* __restrict__ ckx_fw,
                      const float* __restrict__ gkx_bw, const float* __restrict__ ckx_bw)
{
    __shared__ float sA[64][33];
    __shared__ float sW[32][96];
    __shared__ int   sTok[64];
    int dir = blockIdx.y;
    int rt  = blockIdx.x;                // 0..2687
    int t   = rt >> 7;
    int b0  = (rt & 127) << 6;
    int tid = threadIdx.x;
    int tx = tid & 15, ty = tid >> 4;
    float* outp = d_XW0 + ((size_t)(dir * TT + t) * NB + b0) * 96;

    if (t == 10) {                       // hole: identical row for all b
        #pragma unroll
        for (int c = 0; c < 6; c++) {
            int col = tx + 16 * c;
            float v = d_HW[dir * 96 + col];
            #pragma unroll
            for (int r = 0; r < 4; r++) outp[(ty * 4 + r) * 96 + col] = v;
        }
        return;
    }

    const float* Abase = d_TY + ((size_t)t * NB + b0) * 32;
    for (int i = tid; i < 64 * 32; i += 256) sA[i >> 5][i & 31] = Abase[i];
    const float* gkx = dir ? gkx_bw : gkx_fw;
    const float* ckx = dir ? ckx_bw : ckx_fw;
    for (int i = tid; i < 32 * 64; i += 256) sW[i >> 6][i & 63]        = gkx[i];
    for (int i = tid; i < 32 * 32; i += 256) sW[i >> 5][64 + (i & 31)] = ckx[i];
    if (tid < 64) {
        int b = b0 + tid;
        sTok[tid] = (t < 10) ? tok_b[b * 10 + t] : tok_a[b * 10 + (t - 11)];
    }
    __syncthreads();

    float acc[4][6];
    #pragma unroll
    for (int r = 0; r < 4; r++)
        #pragma unroll
        for (int c = 0; c < 6; c++) acc[r][c] = 0.0f;

    #pragma unroll
    for (int k = 0; k < 32; k++) {
        float a[4], bv[6];
        #pragma unroll
        for (int r = 0; r < 4; r++) a[r] = sA[ty * 4 + r][k];
        #pragma unroll
        for (int c = 0; c < 6; c++) bv[c] = sW[k][tx + 16 * c];
        #pragma unroll
        for (int r = 0; r < 4; r++)
            #pragma unroll
            for (int c = 0; c < 6; c++) acc[r][c] = fmaf(a[r], bv[c], acc[r][c]);
    }

    #pragma unroll
    for (int r = 0; r < 4; r++) {
        const float* tw = d_TW + (size_t)sTok[ty * 4 + r] * 192 + dir * 96;
        #pragma unroll
        for (int c = 0; c < 6; c++) {
            int col = tx + 16 * c;
            outp[(ty * 4 + r) * 96 + col] = acc[r][c] + tw[col];
        }
    }
}

// ---------------- K4: fused recurrence (layer0 rec -> xw1 GEMV -> layer1 rec)
// 512 threads = 16 warps; warp = (dir, row); 8 batch rows per block.
// smem: Wh0[2][32][96] | W1x[2][64][96] | Wh1[2][32][96] | B1[2][96] | Y0[8][21*64]
#define SM_WH0 0
#define SM_W1X 6144
#define SM_WH1 18432
#define SM_B1  24576
#define SM_Y0  24768
#define SM_TOTF 35520                       // floats
#define SM_BYTES (SM_TOTF * 4)

__device__ __forceinline__ float sigf(float x)  { return 1.0f / (1.0f + __expf(-x)); }
__device__ __forceinline__ float tanhx(float x) { return 1.0f - 2.0f / (__expf(2.0f * x) + 1.0f); }

__global__ __launch_bounds__(512, 1)
void k_fused(const float* __restrict__ gk_fw0, const float* __restrict__ ck_fw0,
             const float* __restrict__ gk_bw0, const float* __restrict__ ck_bw0,
             const float* __restrict__ gk_fw1, const float* __restrict__ gb_fw1,
             const float* __restrict__ ck_fw1, const float* __restrict__ cb_fw1,
             const float* __restrict__ gk_bw1, const float* __restrict__ gb_bw1,
             const float* __restrict__ ck_bw1, const float* __restrict__ cb_bw1,
             float* __restrict__ out)
{
    extern __shared__ float sm[];
    int tid = threadIdx.x;

    // ---- stage all weights once ----
    for (int i = tid; i < 6144; i += 512) {          // Wh0: layer0 h-part rows 160..191
        int d = i / 3072, rem = i % 3072, k = rem / 96, c = rem % 96;
        const float* gk = d ? gk_bw0 : gk_fw0;
        const float* ck = d ? ck_bw0 : ck_fw0;
        sm[SM_WH0 + i] = (c < 64) ? gk[(160 + k) * 64 + c] : ck[(160 + k) * 32 + (c - 64)];
    }
    for (int i = tid; i < 12288; i += 512) {         // W1x: layer1 x-part rows 0..63
        int d = i / 6144, rem = i % 6144, k = rem / 96, c = rem % 96;
        const float* gk = d ? gk_bw1 : gk_fw1;
        const float* ck = d ? ck_bw1 : ck_fw1;
        sm[SM_W1X + i] = (c < 64) ? gk[k * 64 + c] : ck[k * 32 + (c - 64)];
    }
    for (int i = tid; i < 6144; i += 512) {          // Wh1: layer1 h-part rows 64..95
        int d = i / 3072, rem = i % 3072, k = rem / 96, c = rem % 96;
        const float* gk = d ? gk_bw1 : gk_fw1;
        const float* ck = d ? ck_bw1 : ck_fw1;
        sm[SM_WH1 + i] = (c < 64) ? gk[(64 + k) * 64 + c] : ck[(64 + k) * 32 + (c - 64)];
    }
    if (tid < 192) {                                  // layer1 bias
        int d = tid / 96, c = tid % 96;
        const float* gb = d ? gb_bw1 : gb_fw1;
        const float* cb = d ? cb_bw1 : cb_fw1;
        sm[SM_B1 + tid] = (c < 64) ? gb[c] : cb[c - 64];
    }
    __syncthreads();

    int lane = tid & 31, wid = tid >> 5;
    int dir = wid >> 3, r = wid & 7;
    int b = blockIdx.x * 8 + r;

    // ---- layer0 recurrence (Y0 into smem), XW0 streamed with prefetch ----
    {
        const float* wh = sm + SM_WH0 + dir * 3072;
        float* yrow = sm + SM_Y0 + r * (TT * 64);
        float h = 0.0f;
        int t0 = dir ? 20 : 0;
        const float* xw = d_XW0 + ((size_t)(dir * TT + t0) * NB + b) * 96;
        float nr = xw[lane], nu = xw[32 + lane], nc = xw[64 + lane];
        for (int s = 0; s < 21; s++) {
            int t = dir ? 20 - s : s;
            float ar = nr, au = nu, ac = nc;
            if (s < 20) {                            // prefetch next step
                int t2 = dir ? t - 1 : t + 1;
                const float* xwn = d_XW0 + ((size_t)(dir * TT + t2) * NB + b) * 96;
                nr = xwn[lane]; nu = xwn[32 + lane]; nc = xwn[64 + lane];
            }
            #pragma unroll
            for (int k = 0; k < 32; k++) {
                float hk = __shfl_sync(0xffffffffu, h, k);
                ar = fmaf(hk, wh[k * 96 + lane],      ar);
                au = fmaf(hk, wh[k * 96 + 32 + lane], au);
            }
            float rg = sigf(ar), ug = sigf(au);
            float rh = rg * h;
            #pragma unroll
            for (int k = 0; k < 32; k++) {
                float rk = __shfl_sync(0xffffffffu, rh, k);
                ac = fmaf(rk, wh[k * 96 + 64 + lane], ac);
            }
            float c = tanhx(ac);
            h = fmaf(ug, h - c, c);                  // u*h + (1-u)*c
            yrow[t * 64 + dir * 32 + lane] = h;
        }
    }
    __syncthreads();

    // ---- xw1 GEMV, register-tiled over all 21 steps (reads w1x once) ----
    float accr[21], accu[21], accc[21];
    {
        const float* b1 = sm + SM_B1 + dir * 96;
        float br = b1[lane], bu = b1[32 + lane], bc = b1[64 + lane];
        #pragma unroll
        for (int t = 0; t < 21; t++) { accr[t] = br; accu[t] = bu; accc[t] = bc; }

        const float* w1 = sm + SM_W1X + dir * 6144;
        const float* yrow = sm + SM_Y0 + r * (TT * 64);
        for (int k = 0; k < 64; k++) {
            float wr = w1[k * 96 + lane];
            float wu = w1[k * 96 + 32 + lane];
            float wc = w1[k * 96 + 64 + lane];
            const float* y = yrow + k;
            #pragma unroll
            for (int t = 0; t < 21; t++) {
                float yv = y[t * 64];                // broadcast smem read
                accr[t] = fmaf(yv, wr, accr[t]);
                accu[t] = fmaf(yv, wu, accu[t]);
                accc[t] = fmaf(yv, wc, accc[t]);
            }
        }
    }

    // ---- layer1 recurrence (t statically indexed so acc stays in regs) ----
    {
        const float* wh = sm + SM_WH1 + dir * 3072;
        float h = 0.0f;

        #define GRU1_STEP(T)                                                   \
        {                                                                      \
            float ar = accr[T], au = accu[T], ac = accc[T];                    \
            _Pragma("unroll 8")                                                \
            for (int k = 0; k < 32; k++) {                                     \
                float hk = __shfl_sync(0xffffffffu, h, k);                     \
                ar = fmaf(hk, wh[k * 96 + lane],      ar);                     \
                au = fmaf(hk, wh[k * 96 + 32 + lane], au);                     \
            }                                                                  \
            float rg = sigf(ar), ug = sigf(au);                                \
            float rh = rg * h;                                                 \
            _Pragma("unroll 8")                                                \
            for (int k = 0; k < 32; k++) {                                     \
                float rk = __shfl_sync(0xffffffffu, rh, k);                    \
                ac = fmaf(rk, wh[k * 96 + 64 + lane], ac);                     \
            }                                                                  \
            float c = tanhx(ac);                                               \
            h = fmaf(ug, h - c, c);                                            \
            out[((size_t)b * TT + (T)) * 64 + dir * 32 + lane] = h;            \
        }

        if (dir == 0) {
            #pragma unroll
            for (int s = 0; s < 21; s++) GRU1_STEP(s);
        } else {
            #pragma unroll
            for (int s = 0; s < 21; s++) GRU1_STEP(20 - s);
        }
        #undef GRU1_STEP
    }
}

// ---------------- launch ----------------------------------------------------
extern "C" void kernel_launch(void* const* d_in, const int* in_sizes, int n_in,
                              void* d_out, int out_size)
{
    const int*   tok_b = (const int*)d_in[0];
    const int*   typ_b = (const int*)d_in[1];
    const void*  msk_b = (const void*)d_in[2];
    const int*   tok_a = (const int*)d_in[3];
    const int*   typ_a = (const int*)d_in[4];
    const void*  msk_a = (const void*)d_in[5];
    const float* temb = (const float*)d_in[6];
    const float* yemb = (const float*)d_in[7];
    const float* hole = (const float*)d_in[8];
    const float* gk_fw0 = (const float*)d_in[9];
    const float* gb_fw0 = (const float*)d_in[10];
    const float* ck_fw0 = (const float*)d_in[11];
    const float* cb_fw0 = (const float*)d_in[12];
    const float* gk_bw0 = (const float*)d_in[13];
    const float* gb_bw0 = (const float*)d_in[14];
    const float* ck_bw0 = (const float*)d_in[15];
    const float* cb_bw0 = (const float*)d_in[16];
    const float* gk_fw1 = (const float*)d_in[17];
    const float* gb_fw1 = (const float*)d_in[18];
    const float* ck_fw1 = (const float*)d_in[19];
    const float* cb_fw1 = (const float*)d_in[20];
    const float* gk_bw1 = (const float*)d_in[21];
    const float* gb_bw1 = (const float*)d_in[22];
    const float* ck_bw1 = (const float*)d_in[23];
    const float* cb_bw1 = (const float*)d_in[24];
    float* out = (float*)d_out;

    cudaFuncSetAttribute(k_fused, cudaFuncAttributeMaxDynamicSharedMemorySize, SM_BYTES);

    // 0) detect mask dtype (uint8 vs int32 vs float32)
    k_reset<<<1, 1>>>();
    k_detect<<<148, 256>>>((const unsigned*)msk_b);

    // 1) token table + hole row
    k_tables<<<5001, 192>>>(temb, hole,
                            gk_fw0, gb_fw0, ck_fw0, cb_fw0,
                            gk_bw0, gb_bw0, ck_bw0, cb_bw0);

    // 2) masked type-max embeddings
    k_typemax<<<20480, 256>>>(typ_b, msk_b, typ_a, msk_a, yemb);

    // 3) layer0 x-precompute (type part K=32 + token-table gather)
    k_xw0<<<dim3(2688, 2), 256>>>(tok_b, tok_a,
                                  gk_fw0 + 128 * 64, ck_fw0 + 128 * 32,
                                  gk_bw0 + 128 * 64, ck_bw0 + 128 * 32);

    // 4) fused: layer0 recurrence -> xw1 GEMV -> layer1 recurrence -> out
    k_fused<<<1024, 512, SM_BYTES>>>(gk_fw0, ck_fw0, gk_bw0, ck_bw0,
                                     gk_fw1, gb_fw1, ck_fw1, cb_fw1,
                                     gk_bw1, gb_bw1, ck_bw1, cb_bw1,
                                     out);
}

// round 9
// speedup vs baseline: 1.6525x; 1.1978x over previous
#include <cuda_runtime.h>
#include <math.h>

#define NB 8192
#define TT 21

// ---------------- scratch (static device allocations; no cudaMalloc) -------
__device__ float d_TW[5000 * 192];      // token-part of layer0 x@Wx (+bias), per dir
__device__ float d_HW[2 * 96];          // hole row x@Wx (+bias), per dir
__device__ float d_XW0[2 * TT * NB * 96];
__device__ unsigned d_maskFlags;        // dtype-detection flags for mask buffers

// ---------------- f32x2 helpers --------------------------------------------
typedef unsigned long long u64t;
__device__ __forceinline__ u64t pack2(float lo, float hi) {
    u64t r; asm("mov.b64 %0,{%1,%2};" : "=l"(r) : "f"(lo), "f"(hi)); return r;
}
__device__ __forceinline__ void unpack2(u64t v, float& lo, float& hi) {
    asm("mov.b64 {%0,%1},%2;" : "=f"(lo), "=f"(hi) : "l"(v));
}
__device__ __forceinline__ u64t fma2(u64t a, u64t b, u64t c) {
    u64t d; asm("fma.rn.f32x2 %0,%1,%2,%3;" : "=l"(d) : "l"(a), "l"(b), "l"(c)); return d;
}
__device__ __forceinline__ float sigf(float x)  { return 1.0f / (1.0f + __expf(-x)); }
__device__ __forceinline__ float tanhx(float x) { return 1.0f - 2.0f / (__expf(2.0f * x) + 1.0f); }

// ---------------- K0: mask dtype detection ---------------------------------
__global__ void k_reset() { d_maskFlags = 0u; }

__global__ void k_detect(const unsigned* __restrict__ m) {
    unsigned f = 0;
    for (int i = blockIdx.x * blockDim.x + threadIdx.x; i < 204800;
         i += gridDim.x * blockDim.x) {
        unsigned w = m[i];
        if (w != 0u && w != 1u) f |= 1u;
        if (w != 0u && w != 0x3F800000u) f |= 2u;
    }
    if (f) atomicOr(&d_maskFlags, f);
}

// ---------------- K1: per-vocab token table + hole row ---------------------
__global__ void k_tables(const float* __restrict__ tok_emb,
                         const float* __restrict__ hole,
                         const float* __restrict__ gk_fw, const float* __restrict__ gb_fw,
                         const float* __restrict__ ck_fw, const float* __restrict__ cb_fw,
                         const float* __restrict__ gk_bw, const float* __restrict__ gb_bw,
                         const float* __restrict__ ck_bw, const float* __restrict__ cb_bw)
{
    __shared__ float s[160];
    int v = blockIdx.x;
    int tid = threadIdx.x;              // 0..191
    bool is_hole = (v == 5000);
    int nk = is_hole ? 160 : 128;
    if (tid < nk) s[tid] = is_hole ? hole[tid] : tok_emb[v * 128 + tid];
    __syncthreads();

    int dir = tid / 96, col = tid % 96;
    const float* gk = dir ? gk_bw : gk_fw;
    const float* ck = dir ? ck_bw : ck_fw;
    const float* gb = dir ? gb_bw : gb_fw;
    const float* cb = dir ? cb_bw : cb_fw;
    const float* w;
    int stride;
    float acc;
    if (col < 64) { w = gk + col;        stride = 64; acc = gb[col]; }
    else          { w = ck + (col - 64); stride = 32; acc = cb[col - 64]; }
    #pragma unroll 8
    for (int k = 0; k < nk; k++) acc = fmaf(s[k], w[k * stride], acc);

    if (is_hole) d_HW[tid] = acc;
    else         d_TW[(size_t)v * 192 + tid] = acc;
}

// ---------------- K2: layer0 x-precompute GEMM, typemax fused --------------
__global__ void k_xw0(const int* __restrict__ tok_b, const int* __restrict__ tok_a,
                      const int* __restrict__ typ_b, const void* __restrict__ msk_b,
                      const int* __restrict__ typ_a, const void* __restrict__ msk_a,
                      const float* __restrict__ yemb,
                      const float* __restrict__ gkx_fw, const float* __restrict__ ckx_fw,
                      const float* __restrict__ gkx_bw, const float* __restrict__ ckx_bw)
{
    __shared__ float sA[64][33];
    __shared__ float sW[32][96];
    __shared__ int   sTok[64];
    int dir = blockIdx.y;
    int rt  = blockIdx.x;                // 0..2687
    int t   = rt >> 7;
    int b0  = (rt & 127) << 6;
    int tid = threadIdx.x;
    int tx = tid & 15, ty = tid >> 4;
    float* outp = d_XW0 + ((size_t)(dir * TT + t) * NB + b0) * 96;

    if (t == 10) {                       // hole: identical row for all b
        #pragma unroll
        for (int c = 0; c < 6; c++) {
            int col = tx + 16 * c;
            float v = d_HW[dir * 96 + col];
            #pragma unroll
            for (int r = 0; r < 4; r++) outp[(ty * 4 + r) * 96 + col] = v;
        }
        return;
    }

    // ---- fused masked type-max: one warp computes 8 rows of sA ----
    {
        unsigned flags = d_maskFlags;
        int mode = ((flags & 1u) == 0u) ? 1 : (((flags & 2u) == 0u) ? 2 : 0);
        int wid = tid >> 5, lane = tid & 31;
        int pos = (t < 10) ? t : t - 11;
        const int*  typ = (t < 10) ? typ_b : typ_a;
        const void* msk = (t < 10) ? msk_b : msk_a;
        for (int rr = wid; rr < 64; rr += 8) {
            int bb = b0 + rr;
            int base = (bb * 10 + pos) * 10;
            float m = -3.402823e38f;
            #pragma unroll
            for (int nt = 0; nt < 10; nt++) {
                int id = typ[base + nt];
                bool valid;
                if (mode == 1)      valid = ((const int*)msk)[base + nt] != 0;
                else if (mode == 2) valid = ((const float*)msk)[base + nt] != 0.0f;
                else                valid = ((const unsigned char*)msk)[base + nt] != 0;
                m = fmaxf(m, yemb[id * 32 + lane] + (valid ? 0.0f : -1000.0f));
            }
            sA[rr][lane] = m;
        }
    }

    const float* gkx = dir ? gkx_bw : gkx_fw;
    const float* ckx = dir ? ckx_bw : ckx_fw;
    for (int i = tid; i < 32 * 64; i += 256) sW[i >> 6][i & 63]        = gkx[i];
    for (int i = tid; i < 32 * 32; i += 256) sW[i >> 5][64 + (i & 31)] = ckx[i];
    if (tid < 64) {
        int bb = b0 + tid;
        sTok[tid] = (t < 10) ? tok_b[bb * 10 + t] : tok_a[bb * 10 + (t - 11)];
    }
    __syncthreads();

    float acc[4][6];
    #pragma unroll
    for (int r = 0; r < 4; r++)
        #pragma unroll
        for (int c = 0; c < 6; c++) acc[r][c] = 0.0f;

    #pragma unroll
    for (int k = 0; k < 32; k++) {
        float a[4], bv[6];
        #pragma unroll
        for (int r = 0; r < 4; r++) a[r] = sA[ty * 4 + r][k];
        #pragma unroll
        for (int c = 0; c < 6; c++) bv[c] = sW[k][tx + 16 * c];
        #pragma unroll
        for (int r = 0; r < 4; r++)
            #pragma unroll
            for (int c = 0; c < 6; c++) acc[r][c] = fmaf(a[r], bv[c], acc[r][c]);
    }

    #pragma unroll
    for (int r = 0; r < 4; r++) {
        const float* tw = d_TW + (size_t)sTok[ty * 4 + r] * 192 + dir * 96;
        #pragma unroll
        for (int c = 0; c < 6; c++) {
            int col = tx + 16 * c;
            outp[(ty * 4 + r) * 96 + col] = acc[r][c] + tw[col];
        }
    }
}

// ---------------- K3: fused recurrence (layer0 -> xw1 GEMV -> layer1) ------
// 512 threads = 16 warps; warp = (dir, row); 8 batch rows per block.
// smem (floats):
//  G0R/G0U/C0: k-paired rec0 weights [dir][k2][lane][2]   3 x 2048
//  G1R/G1U/C1: k-paired rec1 weights                      3 x 2048
//  W1X: layer1 x-part [dir][64][96]                       12288
//  B1:  layer1 bias [dir][96]                             192
//  Y:   layer0 output, channel-major [8 rows][64 ch][22]  11264
//  H:   per-warp h/rh broadcast buffers [16][72]          1152
#define SM_G0R 0
#define SM_G0U 2048
#define SM_C0  4096
#define SM_G1R 6144
#define SM_G1U 8192
#define SM_C1  10240
#define SM_W1X 12288
#define SM_B1  24576
#define SM_Y   24768
#define SM_H   36032
#define SM_TOTF 37184
#define SM_BYTES (SM_TOTF * 4)

__global__ __launch_bounds__(512, 1)
void k_fused(const float* __restrict__ gk_fw0, const float* __restrict__ ck_fw0,
             const float* __restrict__ gk_bw0, const float* __restrict__ ck_bw0,
             const float* __restrict__ gk_fw1, const float* __restrict__ gb_fw1,
             const float* __restrict__ ck_fw1, const float* __restrict__ cb_fw1,
             const float* __restrict__ gk_bw1, const float* __restrict__ gb_bw1,
             const float* __restrict__ ck_bw1, const float* __restrict__ cb_bw1,
             float* __restrict__ out)
{
    extern __shared__ float sm[];
    int tid = threadIdx.x;

    // ---- stage all weights once (k-paired layouts for rec) ----
    for (int i = tid; i < 2048; i += 512) {
        int p = i & 1, ln = (i >> 1) & 31, k2 = (i >> 6) & 15, d = i >> 10;
        const float* gk0 = d ? gk_bw0 : gk_fw0;
        const float* ck0 = d ? ck_bw0 : ck_fw0;
        const float* gk1 = d ? gk_bw1 : gk_fw1;
        const float* ck1 = d ? ck_bw1 : ck_fw1;
        int r0 = 160 + 2 * k2 + p;       // layer0 h-part rows
        int r1 = 64 + 2 * k2 + p;        // layer1 h-part rows
        sm[SM_G0R + i] = gk0[r0 * 64 + ln];
        sm[SM_G0U + i] = gk0[r0 * 64 + 32 + ln];
        sm[SM_C0  + i] = ck0[r0 * 32 + ln];
        sm[SM_G1R + i] = gk1[r1 * 64 + ln];
        sm[SM_G1U + i] = gk1[r1 * 64 + 32 + ln];
        sm[SM_C1  + i] = ck1[r1 * 32 + ln];
    }
    for (int i = tid; i < 12288; i += 512) {
        int d = i / 6144, rem = i % 6144, k = rem / 96, c = rem % 96;
        const float* gk1 = d ? gk_bw1 : gk_fw1;
        const float* ck1 = d ? ck_bw1 : ck_fw1;
        sm[SM_W1X + i] = (c < 64) ? gk1[k * 64 + c] : ck1[k * 32 + (c - 64)];
    }
    if (tid < 192) {
        int d = tid / 96, c = tid % 96;
        sm[SM_B1 + tid] = (c < 64) ? (d ? gb_bw1 : gb_fw1)[c]
                                   : (d ? cb_bw1 : cb_fw1)[c - 64];
    }
    __syncthreads();

    int lane = tid & 31, wid = tid >> 5;
    int dir = wid >> 3, r = wid & 7;
    int b = blockIdx.x * 8 + r;
    float* yrow = sm + SM_Y + r * 1408;              // [64 ch][22]
    float* hbuf = sm + SM_H + wid * 72;              // h at +0, rh at +36
    const float* g0r = sm + SM_G0R + dir * 1024;
    const float* g0u = sm + SM_G0U + dir * 1024;
    const float* c0w = sm + SM_C0  + dir * 1024;

    // ---- layer0 recurrence; Y written channel-major into smem ----
    {
        float h = 0.0f;
        int t0 = dir ? 20 : 0;
        const float* xw = d_XW0 + ((size_t)(dir * TT + t0) * NB + b) * 96;
        float nr = xw[lane], nu = xw[32 + lane], nc = xw[64 + lane];
        for (int s = 0; s < 21; s++) {
            int t = dir ? 20 - s : s;
            float xr = nr, xu = nu, xc = nc;
            if (s < 20) {
                int t2 = dir ? t - 1 : t + 1;
                const float* xn = d_XW0 + ((size_t)(dir * TT + t2) * NB + b) * 96;
                nr = xn[lane]; nu = xn[32 + lane]; nc = xn[64 + lane];
            }
            __syncwarp();
            hbuf[lane] = h;
            __syncwarp();
            u64t ar2 = pack2(xr, 0.0f), au2 = pack2(xu, 0.0f);
            #pragma unroll
            for (int k2 = 0; k2 < 16; k2++) {
                u64t hp = *(const u64t*)(hbuf + 2 * k2);
                ar2 = fma2(*(const u64t*)(g0r + (k2 * 32 + lane) * 2), hp, ar2);
                au2 = fma2(*(const u64t*)(g0u + (k2 * 32 + lane) * 2), hp, au2);
            }
            float arl, arh, aul, auh;
            unpack2(ar2, arl, arh); unpack2(au2, aul, auh);
            float rg = sigf(arl + arh), ug = sigf(aul + auh);
            float rh = rg * h;
            hbuf[36 + lane] = rh;
            __syncwarp();
            u64t ac2 = pack2(xc, 0.0f);
            #pragma unroll
            for (int k2 = 0; k2 < 16; k2++) {
                u64t rp = *(const u64t*)(hbuf + 36 + 2 * k2);
                ac2 = fma2(*(const u64t*)(c0w + (k2 * 32 + lane) * 2), rp, ac2);
            }
            float acl, ach; unpack2(ac2, acl, ach);
            float c = tanhx(acl + ach);
            h = fmaf(ug, h - c, c);
            yrow[(dir * 32 + lane) * 22 + t] = h;
        }
    }
    __syncthreads();

    // ---- xw1 GEMV: t-paired f32x2 over channel-major Y ----
    float accr_s[21], accu_s[21], accc_s[21];   // dynamically indexed -> local
    {
        const float* w1 = sm + SM_W1X + dir * 6144;
        float br = sm[SM_B1 + dir * 96 + lane];
        float bu = sm[SM_B1 + dir * 96 + 32 + lane];
        float bc = sm[SM_B1 + dir * 96 + 64 + lane];
        u64t ar2[10], au2[10], ac2[10];
        float ar20 = br, au20 = bu, ac20 = bc;
        #pragma unroll
        for (int tp = 0; tp < 10; tp++) {
            ar2[tp] = pack2(br, br); au2[tp] = pack2(bu, bu); ac2[tp] = pack2(bc, bc);
        }
        for (int k = 0; k < 64; k++) {
            float wr = w1[k * 96 + lane];
            float wu = w1[k * 96 + 32 + lane];
            float wc = w1[k * 96 + 64 + lane];
            u64t wr2 = pack2(wr, wr), wu2 = pack2(wu, wu), wc2 = pack2(wc, wc);
            const u64t* yk = (const u64t*)(yrow + k * 22);
            #pragma unroll
            for (int tp = 0; tp < 10; tp++) {
                u64t yp = yk[tp];
                ar2[tp] = fma2(wr2, yp, ar2[tp]);
                au2[tp] = fma2(wu2, yp, au2[tp]);
                ac2[tp] = fma2(wc2, yp, ac2[tp]);
            }
            float y20 = yrow[k * 22 + 20];
            ar20 = fmaf(wr, y20, ar20);
            au20 = fmaf(wu, y20, au20);
            ac20 = fmaf(wc, y20, ac20);
        }
        // unpack into step-ordered arrays: step s handles t = dir?20-s:s
        if (dir == 0) {
            #pragma unroll
            for (int tp = 0; tp < 10; tp++) {
                unpack2(ar2[tp], accr_s[2 * tp], accr_s[2 * tp + 1]);
                unpack2(au2[tp], accu_s[2 * tp], accu_s[2 * tp + 1]);
                unpack2(ac2[tp], accc_s[2 * tp], accc_s[2 * tp + 1]);
            }
            accr_s[20] = ar20; accu_s[20] = au20; accc_s[20] = ac20;
        } else {
            #pragma unroll
            for (int tp = 0; tp < 10; tp++) {
                unpack2(ar2[tp], accr_s[20 - 2 * tp], accr_s[19 - 2 * tp]);
                unpack2(au2[tp], accu_s[20 - 2 * tp], accu_s[19 - 2 * tp]);
                unpack2(ac2[tp], accc_s[20 - 2 * tp], accc_s[19 - 2 * tp]);
            }
            accr_s[0] = ar20; accu_s[0] = au20; accc_s[0] = ac20;
        }
    }

    // ---- layer1 recurrence (rolled; acc in local, trivial traffic) ----
    {
        const float* g1r = sm + SM_G1R + dir * 1024;
        const float* g1u = sm + SM_G1U + dir * 1024;
        const float* c1w = sm + SM_C1  + dir * 1024;
        float h = 0.0f;
        for (int s = 0; s < 21; s++) {
            float xr = accr_s[s], xu = accu_s[s], xc = accc_s[s];
            __syncwarp();
            hbuf[lane] = h;
            __syncwarp();
            u64t ar2 = pack2(xr, 0.0f), au2 = pack2(xu, 0.0f);
            #pragma unroll
            for (int k2 = 0; k2 < 16; k2++) {
                u64t hp = *(const u64t*)(hbuf + 2 * k2);
                ar2 = fma2(*(const u64t*)(g1r + (k2 * 32 + lane) * 2), hp, ar2);
                au2 = fma2(*(const u64t*)(g1u + (k2 * 32 + lane) * 2), hp, au2);
            }
            float arl, arh, aul, auh;
            unpack2(ar2, arl, arh); unpack2(au2, aul, auh);
            float rg = sigf(arl + arh), ug = sigf(aul + auh);
            float rh = rg * h;
            hbuf[36 + lane] = rh;
            __syncwarp();
            u64t ac2 = pack2(xc, 0.0f);
            #pragma unroll
            for (int k2 = 0; k2 < 16; k2++) {
                u64t rp = *(const u64t*)(hbuf + 36 + 2 * k2);
                ac2 = fma2(*(const u64t*)(c1w + (k2 * 32 + lane) * 2), rp, ac2);
            }
            float acl, ach; unpack2(ac2, acl, ach);
            float c = tanhx(acl + ach);
            h = fmaf(ug, h - c, c);
            int t = dir ? 20 - s : s;
            out[((size_t)b * TT + t) * 64 + dir * 32 + lane] = h;
        }
    }
}

// ---------------- launch ----------------------------------------------------
extern "C" void kernel_launch(void* const* d_in, const int* in_sizes, int n_in,
                              void* d_out, int out_size)
{
    const int*   tok_b = (const int*)d_in[0];
    const int*   typ_b = (const int*)d_in[1];
    const void*  msk_b = (const void*)d_in[2];
    const int*   tok_a = (const int*)d_in[3];
    const int*   typ_a = (const int*)d_in[4];
    const void*  msk_a = (const void*)d_in[5];
    const float* temb = (const float*)d_in[6];
    const float* yemb = (const float*)d_in[7];
    const float* hole = (const float*)d_in[8];
    const float* gk_fw0 = (const float*)d_in[9];
    const float* gb_fw0 = (const float*)d_in[10];
    const float* ck_fw0 = (const float*)d_in[11];
    const float* cb_fw0 = (const float*)d_in[12];
    const float* gk_bw0 = (const float*)d_in[13];
    const float* gb_bw0 = (const float*)d_in[14];
    const float* ck_bw0 = (const float*)d_in[15];
    const float* cb_bw0 = (const float*)d_in[16];
    const float* gk_fw1 = (const float*)d_in[17];
    const float* gb_fw1 = (const float*)d_in[18];
    const float* ck_fw1 = (const float*)d_in[19];
    const float* cb_fw1 = (const float*)d_in[20];
    const float* gk_bw1 = (const float*)d_in[21];
    const float* gb_bw1 = (const float*)d_in[22];
    const float* ck_bw1 = (const float*)d_in[23];
    const float* cb_bw1 = (const float*)d_in[24];
    float* out = (float*)d_out;

    cudaFuncSetAttribute(k_fused, cudaFuncAttributeMaxDynamicSharedMemorySize, SM_BYTES);

    // 0) detect mask dtype (uint8 vs int32 vs float32)
    k_reset<<<1, 1>>>();
    k_detect<<<148, 256>>>((const unsigned*)msk_b);

    // 1) token table + hole row
    k_tables<<<5001, 192>>>(temb, hole,
                            gk_fw0, gb_fw0, ck_fw0, cb_fw0,
                            gk_bw0, gb_bw0, ck_bw0, cb_bw0);

    // 2) layer0 x-precompute with fused masked type-max
    k_xw0<<<dim3(2688, 2), 256>>>(tok_b, tok_a,
                                  typ_b, msk_b, typ_a, msk_a, yemb,
                                  gk_fw0 + 128 * 64, ck_fw0 + 128 * 32,
                                  gk_bw0 + 128 * 64, ck_bw0 + 128 * 32);

    // 3) fused: layer0 recurrence -> xw1 GEMV -> layer1 recurrence -> out
    k_fused<<<1024, 512, SM_BYTES>>>(gk_fw0, ck_fw0, gk_bw0, ck_bw0,
                                     gk_fw1, gb_fw1, ck_fw1, cb_fw1,
                                     gk_bw1, gb_bw1, ck_bw1, cb_bw1,
                                     out);
}